// round 1
// baseline (speedup 1.0000x reference)
#include <cuda_runtime.h>

// out = y where 0 < y <= 1 else 0, y = x * w[col] + b[col]
// x: [B=8192, D=4096] f32, w/b: [4096] f32. Pure HBM-bound elementwise.

#define D_DIM 4096
#define VEC 4
#define D_VEC (D_DIM / VEC)   // 1024, power of two

__global__ void __launch_bounds__(256)
gegate_kernel(const float4* __restrict__ x,
              const float4* __restrict__ w,
              const float4* __restrict__ b,
              float4* __restrict__ out,
              int n_vec)
{
    int idx = blockIdx.x * blockDim.x + threadIdx.x;
    if (idx >= n_vec) return;

    int col = idx & (D_VEC - 1);          // column in float4 units

    float4 xv = x[idx];
    float4 wv = __ldg(&w[col]);
    float4 bv = __ldg(&b[col]);

    float4 y;
    y.x = fmaf(xv.x, wv.x, bv.x);
    y.y = fmaf(xv.y, wv.y, bv.y);
    y.z = fmaf(xv.z, wv.z, bv.z);
    y.w = fmaf(xv.w, wv.w, bv.w);

    y.x = (y.x > 0.0f && y.x <= 1.0f) ? y.x : 0.0f;
    y.y = (y.y > 0.0f && y.y <= 1.0f) ? y.y : 0.0f;
    y.z = (y.z > 0.0f && y.z <= 1.0f) ? y.z : 0.0f;
    y.w = (y.w > 0.0f && y.w <= 1.0f) ? y.w : 0.0f;

    out[idx] = y;
}

extern "C" void kernel_launch(void* const* d_in, const int* in_sizes, int n_in,
                              void* d_out, int out_size)
{
    const float4* x = (const float4*)d_in[0];
    const float4* w = (const float4*)d_in[1];
    const float4* b = (const float4*)d_in[2];
    float4* out = (float4*)d_out;

    int n_vec = out_size / VEC;           // 8192*4096/4 = 8388608
    int threads = 256;
    int blocks = (n_vec + threads - 1) / threads;

    gegate_kernel<<<blocks, threads>>>(x, w, b, out, n_vec);
}

// round 2
// speedup vs baseline: 1.0537x; 1.0537x over previous
#include <cuda_runtime.h>

// out = y where 0 < y <= 1 else 0, y = x * w[col] + b[col]
// x: [B=8192, D=4096] f32, w/b: [4096] f32. Pure HBM-bound elementwise.
// R2: 4 float4 per thread, front-batched loads (MLP_p1=4), streaming hints.

#define D_DIM 4096
#define VEC 4
#define D_VEC (D_DIM / VEC)   // 1024, power of two
#define ITEMS 4               // float4s per thread
#define THREADS 256

__device__ __forceinline__ float4 gate4(float4 xv, float4 wv, float4 bv)
{
    float4 y;
    y.x = fmaf(xv.x, wv.x, bv.x);
    y.y = fmaf(xv.y, wv.y, bv.y);
    y.z = fmaf(xv.z, wv.z, bv.z);
    y.w = fmaf(xv.w, wv.w, bv.w);
    y.x = (y.x > 0.0f && y.x <= 1.0f) ? y.x : 0.0f;
    y.y = (y.y > 0.0f && y.y <= 1.0f) ? y.y : 0.0f;
    y.z = (y.z > 0.0f && y.z <= 1.0f) ? y.z : 0.0f;
    y.w = (y.w > 0.0f && y.w <= 1.0f) ? y.w : 0.0f;
    return y;
}

__global__ void __launch_bounds__(THREADS)
gegate_kernel(const float4* __restrict__ x,
              const float4* __restrict__ w,
              const float4* __restrict__ b,
              float4* __restrict__ out)
{
    // Each block covers THREADS*ITEMS consecutive float4s; thread t handles
    // base + t + i*THREADS (fully coalesced, 4 independent DRAM loads in flight).
    int base = blockIdx.x * (THREADS * ITEMS) + threadIdx.x;

    float4 xv[ITEMS];
    #pragma unroll
    for (int i = 0; i < ITEMS; i++)
        xv[i] = __ldcs(&x[base + i * THREADS]);   // streaming: no L2 reuse

    #pragma unroll
    for (int i = 0; i < ITEMS; i++) {
        int idx = base + i * THREADS;
        int col = idx & (D_VEC - 1);
        float4 wv = __ldg(&w[col]);
        float4 bv = __ldg(&b[col]);
        __stcs(&out[idx], gate4(xv[i], wv, bv));
    }
}

extern "C" void kernel_launch(void* const* d_in, const int* in_sizes, int n_in,
                              void* d_out, int out_size)
{
    const float4* x = (const float4*)d_in[0];
    const float4* w = (const float4*)d_in[1];
    const float4* b = (const float4*)d_in[2];
    float4* out = (float4*)d_out;

    int n_vec = out_size / VEC;                       // 8388608
    int blocks = n_vec / (THREADS * ITEMS);           // 8192 exactly

    gegate_kernel<<<blocks, THREADS>>>(x, w, b, out);
}